// round 7
// baseline (speedup 1.0000x reference)
#include <cuda_runtime.h>
#include <cuda_bf16.h>
#include <cstdint>

// Problem geometry
#define MROWS 8192          // 2*4096 rows of x
#define INSZ  4096          // input features
#define KF    512           // folded K dim (INSZ/8)
#define UNITS 4096          // output features

// Scratch (device globals: allocation-free rule)
__device__ __align__(256) __nv_bfloat16 g_xh[MROWS * KF];   // 8 MB
__device__ __align__(256) __nv_bfloat16 g_xl[MROWS * KF];   // 8 MB
__device__ __align__(256) __nv_bfloat16 g_kt[UNITS * KF];   // 4 MB, Kt[n][k] = K[k][n]

// ---------------------------------------------------------------------------
// helpers
// ---------------------------------------------------------------------------
static __device__ __forceinline__ uint32_t smem_u32(const void* p) {
    uint32_t a;
    asm("{ .reg .u64 t; cvta.to.shared.u64 t, %1; cvt.u32.u64 %0, t; }"
        : "=r"(a) : "l"(p));
    return a;
}

static __device__ __forceinline__ void cp_async16(uint32_t dst, const void* src) {
    asm volatile("cp.async.cg.shared.global [%0], [%1], 16;"
                 :: "r"(dst), "l"(src) : "memory");
}
#define CP_COMMIT()  asm volatile("cp.async.commit_group;" ::: "memory")
#define CP_WAIT0()   asm volatile("cp.async.wait_group 0;" ::: "memory")

static __device__ __forceinline__ uint32_t lds32(uint32_t addr) {
    uint32_t v;
    asm volatile("ld.shared.b32 %0, [%1];" : "=r"(v) : "r"(addr));
    return v;
}

static __device__ __forceinline__ void mma16816(float* d, const uint32_t* a,
                                                uint32_t b0, uint32_t b1) {
    asm volatile(
        "mma.sync.aligned.m16n8k16.row.col.f32.bf16.bf16.f32 "
        "{%0,%1,%2,%3}, {%4,%5,%6,%7}, {%8,%9}, {%0,%1,%2,%3};"
        : "+f"(d[0]), "+f"(d[1]), "+f"(d[2]), "+f"(d[3])
        : "r"(a[0]), "r"(a[1]), "r"(a[2]), "r"(a[3]), "r"(b0), "r"(b1));
}

// ---------------------------------------------------------------------------
// Kernel 1: fold x[8192,4096] -> xr[8192,512], split into bf16 hi/lo
//   xr[m,q] = sum_{j<8} x[m, q + 512*j]
// ---------------------------------------------------------------------------
__global__ void fold_kernel(const float* __restrict__ x) {
    int idx = blockIdx.x * blockDim.x + threadIdx.x;   // 0 .. 8192*512-1
    int m = idx >> 9;
    int q = idx & 511;
    const float* p = x + (size_t)m * INSZ + q;
    float v = 0.0f;
#pragma unroll
    for (int j = 0; j < 8; j++) v += p[j * 512];
    __nv_bfloat16 h = __float2bfloat16(v);
    float lo = v - __bfloat162float(h);
    g_xh[idx] = h;
    g_xl[idx] = __float2bfloat16(lo);
}

// ---------------------------------------------------------------------------
// Kernel 2: transpose-convert weights (INT32 storage! harness promotes int8)
//   K[512,4096] -> Kt bf16 [4096,512]
// ---------------------------------------------------------------------------
__global__ void kt_kernel(const int* __restrict__ kern) {
    __shared__ int tile[32][33];
    int n0 = blockIdx.x * 32;   // 0..4095
    int k0 = blockIdx.y * 32;   // 0..511
    tile[threadIdx.y][threadIdx.x] =
        kern[(size_t)(k0 + threadIdx.y) * UNITS + n0 + threadIdx.x];
    __syncthreads();
    int n = n0 + threadIdx.y;
    int k = k0 + threadIdx.x;
    g_kt[(size_t)n * KF + k] = __float2bfloat16((float)tile[threadIdx.x][threadIdx.y]);
}

// ---------------------------------------------------------------------------
// Kernel 3: GEMM  y[8192,4096] = [xh;xl] @ [Kt;Kt]^T  via mma.sync bf16
//   CTA 128x128, BK=32, 2-stage cp.async pipeline, 8 warps (4m x 2n),
//   warp tile 32x64, m16n8k16, direct LDS.32 fragment loads (documented
//   layout). KPAD=40 (20-word stride) keeps LDS conflict-free.
// ---------------------------------------------------------------------------
#define BM 128
#define BN 128
#define BK 32
#define KPAD 40
#define GEMM_THREADS 256
#define NITER 32                // 2 passes * (512/32)

__global__ void __launch_bounds__(GEMM_THREADS)
gemm_kernel(float* __restrict__ y) {
    __shared__ __align__(16) __nv_bfloat16 As[2][BM * KPAD];  // 2 x 10 KB
    __shared__ __align__(16) __nv_bfloat16 Bs[2][BN * KPAD];  // 2 x 10 KB

    const int tid  = threadIdx.x;
    const int wid  = tid >> 5;
    const int lane = tid & 31;
    const int wm   = wid >> 1;          // 0..3  (m)
    const int wn   = wid & 1;           // 0..1  (n)

    const int bn = blockIdx.x;          // 0..31
    const int bm = blockIdx.y;          // 0..63

    const __nv_bfloat16* bbase = g_kt + (size_t)bn * BN * KF;

    const int c0  = tid;                // 0..255
    const int c1  = tid + 256;          // 256..511
    const int ar0 = c0 >> 2, ac0 = (c0 & 3) * 8;
    const int ar1 = c1 >> 2, ac1 = (c1 & 3) * 8;

    const uint32_t sA0 = smem_u32(As[0]);
    const uint32_t sA1 = smem_u32(As[1]);
    const uint32_t sB0 = smem_u32(Bs[0]);
    const uint32_t sB1 = smem_u32(Bs[1]);

    float acc[2][8][4];
#pragma unroll
    for (int i = 0; i < 2; i++)
#pragma unroll
        for (int j = 0; j < 8; j++)
#pragma unroll
            for (int k = 0; k < 4; k++) acc[i][j][k] = 0.0f;

    auto load_tiles = [&](int it, int buf) {
        const __nv_bfloat16* ab =
            ((it < 16) ? g_xh : g_xl) + (size_t)bm * BM * KF;
        const int kc = (it & 15) * BK;
        uint32_t da = buf ? sA1 : sA0;
        uint32_t db = buf ? sB1 : sB0;
        cp_async16(da + (uint32_t)(ar0 * KPAD + ac0) * 2,
                   ab + (size_t)ar0 * KF + kc + ac0);
        cp_async16(da + (uint32_t)(ar1 * KPAD + ac1) * 2,
                   ab + (size_t)ar1 * KF + kc + ac1);
        cp_async16(db + (uint32_t)(ar0 * KPAD + ac0) * 2,
                   bbase + (size_t)ar0 * KF + kc + ac0);
        cp_async16(db + (uint32_t)(ar1 * KPAD + ac1) * 2,
                   bbase + (size_t)ar1 * KF + kc + ac1);
    };

    load_tiles(0, 0);
    CP_COMMIT();

    // documented m16n8k16 lane decomposition
    const int g = lane >> 2;            // 0..7
    const int c = (lane & 3) * 2;       // 0,2,4,6

#pragma unroll 1
    for (int it = 0; it < NITER; it++) {
        const int buf = it & 1;
        CP_WAIT0();
        __syncthreads();
        if (it + 1 < NITER) {
            load_tiles(it + 1, buf ^ 1);
            CP_COMMIT();
        }

        const uint32_t a_base = buf ? sA1 : sA0;
        const uint32_t b_base = buf ? sB1 : sB0;

#pragma unroll
        for (int ks = 0; ks < 2; ks++) {
            const int kb = ks * 16;
            uint32_t af[2][4];
#pragma unroll
            for (int mi = 0; mi < 2; mi++) {
                int r0 = wm * 32 + mi * 16 + g;
                af[mi][0] = lds32(a_base + (uint32_t)(r0       * KPAD + kb + c)     * 2);
                af[mi][1] = lds32(a_base + (uint32_t)((r0 + 8) * KPAD + kb + c)     * 2);
                af[mi][2] = lds32(a_base + (uint32_t)(r0       * KPAD + kb + c + 8) * 2);
                af[mi][3] = lds32(a_base + (uint32_t)((r0 + 8) * KPAD + kb + c + 8) * 2);
            }
            uint32_t bfr[8][2];
#pragma unroll
            for (int ni = 0; ni < 8; ni++) {
                int nr = wn * 64 + ni * 8 + g;
                bfr[ni][0] = lds32(b_base + (uint32_t)(nr * KPAD + kb + c)     * 2);
                bfr[ni][1] = lds32(b_base + (uint32_t)(nr * KPAD + kb + c + 8) * 2);
            }
#pragma unroll
            for (int mi = 0; mi < 2; mi++)
#pragma unroll
                for (int ni = 0; ni < 8; ni++)
                    mma16816(acc[mi][ni], af[mi], bfr[ni][0], bfr[ni][1]);
        }
    }

    // ---- epilogue: direct float2 stores (documented D layout) ----
    const size_t row0 = (size_t)bm * BM + wm * 32;
    const int    col0 = bn * BN + wn * 64;
#pragma unroll
    for (int mi = 0; mi < 2; mi++) {
#pragma unroll
        for (int ni = 0; ni < 8; ni++) {
            float* p0 = y + (row0 + mi * 16 + g)     * UNITS + col0 + ni * 8 + c;
            float* p1 = y + (row0 + mi * 16 + g + 8) * UNITS + col0 + ni * 8 + c;
            *(float2*)p0 = make_float2(acc[mi][ni][0], acc[mi][ni][1]);
            *(float2*)p1 = make_float2(acc[mi][ni][2], acc[mi][ni][3]);
        }
    }
}

// ---------------------------------------------------------------------------
// Launch — x is the larger buffer (33.5M vs 2.1M elements)
// ---------------------------------------------------------------------------
extern "C" void kernel_launch(void* const* d_in, const int* in_sizes, int n_in,
                              void* d_out, int out_size) {
    const float* x;
    const int*   kern;
    if (in_sizes[0] >= in_sizes[1]) {
        x    = (const float*)d_in[0];
        kern = (const int*)d_in[1];
    } else {
        kern = (const int*)d_in[0];
        x    = (const float*)d_in[1];
    }
    float* y = (float*)d_out;

    fold_kernel<<<(MROWS * KF) / 256, 256>>>(x);
    kt_kernel<<<dim3(UNITS / 32, KF / 32), dim3(32, 32)>>>(kern);
    gemm_kernel<<<dim3(UNITS / BN, MROWS / BM), GEMM_THREADS>>>(y);
}

// round 8
// speedup vs baseline: 1.6676x; 1.6676x over previous
#include <cuda_runtime.h>
#include <cstdint>

// Problem geometry
#define MROWS 8192          // 2*4096 rows of x
#define INSZ  4096          // input features
#define KF    512           // folded K dim (INSZ/8)
#define UNITS 4096          // output features

// Scratch (device globals: allocation-free rule)
__device__ __align__(256) int8_t g_xh[MROWS * KF];    // 4 MB  hi bytes of quantized xr
__device__ __align__(256) int8_t g_xl[MROWS * KF];    // 4 MB  lo bytes
__device__ __align__(256) int8_t g_w64[UNITS * KF];   // 2 MB  Wt[n][k] = 64*w
__device__ __align__(256) int8_t g_w1 [UNITS * KF];   // 2 MB  Wt[n][k] = w
__device__ __align__(256) float  g_scale[MROWS];      // per-row quant scale

// ---------------------------------------------------------------------------
// helpers
// ---------------------------------------------------------------------------
static __device__ __forceinline__ uint32_t smem_u32(const void* p) {
    uint32_t a;
    asm("{ .reg .u64 t; cvta.to.shared.u64 t, %1; cvt.u32.u64 %0, t; }"
        : "=r"(a) : "l"(p));
    return a;
}

static __device__ __forceinline__ void cp_async16(uint32_t dst, const void* src) {
    asm volatile("cp.async.cg.shared.global [%0], [%1], 16;"
                 :: "r"(dst), "l"(src) : "memory");
}
#define CP_COMMIT()  asm volatile("cp.async.commit_group;" ::: "memory")
#define CP_WAIT0()   asm volatile("cp.async.wait_group 0;" ::: "memory")

static __device__ __forceinline__ uint32_t lds32(uint32_t addr) {
    uint32_t v;
    asm volatile("ld.shared.b32 %0, [%1];" : "=r"(v) : "r"(addr));
    return v;
}

static __device__ __forceinline__ void mma16832_s8(int* d, const uint32_t* a,
                                                   uint32_t b0, uint32_t b1) {
    asm volatile(
        "mma.sync.aligned.m16n8k32.row.col.s32.s8.s8.s32 "
        "{%0,%1,%2,%3}, {%4,%5,%6,%7}, {%8,%9}, {%0,%1,%2,%3};"
        : "+r"(d[0]), "+r"(d[1]), "+r"(d[2]), "+r"(d[3])
        : "r"(a[0]), "r"(a[1]), "r"(a[2]), "r"(a[3]), "r"(b0), "r"(b1));
}

// ---------------------------------------------------------------------------
// Kernel 1: fold + quantize. One block (512 thr) per row m.
//   xr[m,q] = sum_{j<8} x[m, q+512j];  s = rowmax/8191;  qv = rn(xr/s)
//   h = qv >> 6 (arith), l = qv - 64h in [0,63];  store h, l int8.
// ---------------------------------------------------------------------------
__global__ void __launch_bounds__(512)
fold_quant_kernel(const float* __restrict__ x) {
    __shared__ float red[512];
    const int m = blockIdx.x;
    const int q = threadIdx.x;
    const float* p = x + (size_t)m * INSZ + q;
    float v = 0.0f;
#pragma unroll
    for (int j = 0; j < 8; j++) v += p[j * 512];

    red[q] = fabsf(v);
    __syncthreads();
#pragma unroll
    for (int s = 256; s > 0; s >>= 1) {
        if (q < s) red[q] = fmaxf(red[q], red[q + s]);
        __syncthreads();
    }
    const float mx = red[0];
    const float sq = (mx > 0.0f) ? (mx * (1.0f / 8191.0f)) : 1.0f;
    if (q == 0) g_scale[m] = sq;

    int qv = __float2int_rn(v / sq);          // in [-8191, 8191]
    int h  = qv >> 6;                         // [-128, 127]
    int l  = qv - (h << 6);                   // [0, 63]
    g_xh[(size_t)m * KF + q] = (int8_t)h;
    g_xl[(size_t)m * KF + q] = (int8_t)l;
}

// ---------------------------------------------------------------------------
// Kernel 2: transpose weights (int32 storage) -> two int8 operand matrices
//   g_w64[n][k] = 64*w[k][n],  g_w1[n][k] = w[k][n]
// ---------------------------------------------------------------------------
__global__ void ktq_kernel(const int* __restrict__ kern) {
    __shared__ int tile[32][33];
    int n0 = blockIdx.x * 32;   // 0..4095
    int k0 = blockIdx.y * 32;   // 0..511
    tile[threadIdx.y][threadIdx.x] =
        kern[(size_t)(k0 + threadIdx.y) * UNITS + n0 + threadIdx.x];
    __syncthreads();
    int n = n0 + threadIdx.y;
    int k = k0 + threadIdx.x;
    int w = tile[threadIdx.x][threadIdx.y];
    g_w64[(size_t)n * KF + k] = (int8_t)(w * 64);
    g_w1 [(size_t)n * KF + k] = (int8_t)w;
}

// ---------------------------------------------------------------------------
// Kernel 3: GEMM  acc[m,n] = sum_k h*(64w) + l*w  (int8 IMMA, int32 acc)
//   y = s_m * acc.  CTA 128x128, BK=64 bytes, 2-stage cp.async, 8 warps
//   (4m x 2n), warp tile 32x64, m16n8k32, direct LDS.32 fragments.
//   Row stride 80 B (20 words) keeps fragment LDS conflict-free.
// ---------------------------------------------------------------------------
#define BM 128
#define BN 128
#define BK 64                   // bytes (= k elements, int8)
#define RS 80                   // smem row stride in bytes
#define GEMM_THREADS 256
#define NITER 16                // 2 passes * (512/64)

__global__ void __launch_bounds__(GEMM_THREADS)
gemm_kernel(float* __restrict__ y) {
    __shared__ __align__(16) int8_t As[2][BM * RS];   // 2 x 10 KB
    __shared__ __align__(16) int8_t Bs[2][BN * RS];   // 2 x 10 KB

    const int tid  = threadIdx.x;
    const int wid  = tid >> 5;
    const int lane = tid & 31;
    const int wm   = wid >> 1;          // 0..3  (m)
    const int wn   = wid & 1;           // 0..1  (n)

    const int bn = blockIdx.x;          // 0..31
    const int bm = blockIdx.y;          // 0..63

    // cp.async: 512 chunks of 16B per tile -> 2 per thread
    const int ch0 = tid;                // 0..255
    const int ch1 = tid + 256;          // 256..511
    const int r0c = ch0 >> 2, b0c = (ch0 & 3) * 16;
    const int r1c = ch1 >> 2, b1c = (ch1 & 3) * 16;

    const uint32_t sA0 = smem_u32(As[0]);
    const uint32_t sA1 = smem_u32(As[1]);
    const uint32_t sB0 = smem_u32(Bs[0]);
    const uint32_t sB1 = smem_u32(Bs[1]);

    int acc[2][8][4];
#pragma unroll
    for (int i = 0; i < 2; i++)
#pragma unroll
        for (int j = 0; j < 8; j++)
#pragma unroll
            for (int k = 0; k < 4; k++) acc[i][j][k] = 0;

    auto load_tiles = [&](int it, int buf) {
        const bool lo = (it >= 8);
        const int8_t* ab = (lo ? g_xl  : g_xh ) + (size_t)bm * BM * KF;
        const int8_t* bb = (lo ? g_w1  : g_w64) + (size_t)bn * BN * KF;
        const int kc = (it & 7) * BK;
        uint32_t da = buf ? sA1 : sA0;
        uint32_t db = buf ? sB1 : sB0;
        cp_async16(da + (uint32_t)(r0c * RS + b0c), ab + (size_t)r0c * KF + kc + b0c);
        cp_async16(da + (uint32_t)(r1c * RS + b1c), ab + (size_t)r1c * KF + kc + b1c);
        cp_async16(db + (uint32_t)(r0c * RS + b0c), bb + (size_t)r0c * KF + kc + b0c);
        cp_async16(db + (uint32_t)(r1c * RS + b1c), bb + (size_t)r1c * KF + kc + b1c);
    };

    load_tiles(0, 0);
    CP_COMMIT();

    // m16n8k32 lane decomposition: g = row/col group, c4 = k byte offset
    const int g  = lane >> 2;           // 0..7
    const int c4 = (lane & 3) * 4;      // 0,4,8,12

#pragma unroll 1
    for (int it = 0; it < NITER; it++) {
        const int buf = it & 1;
        CP_WAIT0();
        __syncthreads();
        if (it + 1 < NITER) {
            load_tiles(it + 1, buf ^ 1);
            CP_COMMIT();
        }

        const uint32_t a_base = buf ? sA1 : sA0;
        const uint32_t b_base = buf ? sB1 : sB0;

#pragma unroll
        for (int ks = 0; ks < 2; ks++) {        // two k32 steps in BK=64
            const int kb = ks * 32;
            // A frags: a0=A[g][kb+c4..+3], a1=A[g+8][...], a2/a3 at +16
            uint32_t af[2][4];
#pragma unroll
            for (int mi = 0; mi < 2; mi++) {
                int r0 = wm * 32 + mi * 16 + g;
                af[mi][0] = lds32(a_base + (uint32_t)(r0       * RS + kb + c4));
                af[mi][1] = lds32(a_base + (uint32_t)((r0 + 8) * RS + kb + c4));
                af[mi][2] = lds32(a_base + (uint32_t)(r0       * RS + kb + c4 + 16));
                af[mi][3] = lds32(a_base + (uint32_t)((r0 + 8) * RS + kb + c4 + 16));
            }
            // B frags: b0=B[n][kb+c4..+3], b1 at +16  (Bs[n][k], k contiguous)
            uint32_t bfr[8][2];
#pragma unroll
            for (int ni = 0; ni < 8; ni++) {
                int nr = wn * 64 + ni * 8 + g;
                bfr[ni][0] = lds32(b_base + (uint32_t)(nr * RS + kb + c4));
                bfr[ni][1] = lds32(b_base + (uint32_t)(nr * RS + kb + c4 + 16));
            }
#pragma unroll
            for (int mi = 0; mi < 2; mi++)
#pragma unroll
                for (int ni = 0; ni < 8; ni++)
                    mma16832_s8(acc[mi][ni], af[mi], bfr[ni][0], bfr[ni][1]);
        }
    }

    // ---- epilogue: y = s_row * float(acc), float2 stores ----
    const size_t row0 = (size_t)bm * BM + wm * 32;
    const int    col0 = bn * BN + wn * 64;
#pragma unroll
    for (int mi = 0; mi < 2; mi++) {
        const size_t ra = row0 + mi * 16 + g;
        const size_t rb = ra + 8;
        const float  sa = g_scale[ra];
        const float  sb = g_scale[rb];
#pragma unroll
        for (int ni = 0; ni < 8; ni++) {
            float* p0 = y + ra * UNITS + col0 + ni * 8 + (c4 >> 1);
            float* p1 = y + rb * UNITS + col0 + ni * 8 + (c4 >> 1);
            *(float2*)p0 = make_float2(sa * (float)acc[mi][ni][0],
                                       sa * (float)acc[mi][ni][1]);
            *(float2*)p1 = make_float2(sb * (float)acc[mi][ni][2],
                                       sb * (float)acc[mi][ni][3]);
        }
    }
}

// ---------------------------------------------------------------------------
// Launch — x is the larger buffer (33.5M vs 2.1M elements)
// ---------------------------------------------------------------------------
extern "C" void kernel_launch(void* const* d_in, const int* in_sizes, int n_in,
                              void* d_out, int out_size) {
    const float* x;
    const int*   kern;
    if (in_sizes[0] >= in_sizes[1]) {
        x    = (const float*)d_in[0];
        kern = (const int*)d_in[1];
    } else {
        kern = (const int*)d_in[0];
        x    = (const float*)d_in[1];
    }
    float* y = (float*)d_out;

    fold_quant_kernel<<<MROWS, 512>>>(x);
    ktq_kernel<<<dim3(UNITS / 32, KF / 32), dim3(32, 32)>>>(kern);
    gemm_kernel<<<dim3(UNITS / BN, MROWS / BM), GEMM_THREADS>>>(y);
}